// round 10
// baseline (speedup 1.0000x reference)
#include <cuda_runtime.h>
#include <cstdint>

// LoRA linear via rank-16 factor:
//   t   = x @ A^T   : [16384,4096] @ [4096,16] -> [16384,16]   (stage 1, 3xTF32 mma.sync)
//   out = t @ B^T   : [16384,16]   @ [16,4096] -> [16384,4096] (stage 2, f32x2)

#define D 4096
#define R 16
#define ROWS_TOTAL 16384
#define KC 64
#define NCH (D / KC)      // 64
#define AT_STRIDE 24      // transposed A tile row stride (u32) -> conflict-free B frags
#define AT_WORDS (KC * AT_STRIDE)          // 1536 u32 per tile
#define S1_SMEM (3 * 16384 + 4 * AT_WORDS * 4)   // 49152 + 24576 = 73728

typedef unsigned long long u64;

__device__ float g_t[ROWS_TOTAL * R];   // 1 MB scratch (fully overwritten)

// ---------------- helpers ----------------
__device__ __forceinline__ u64 fma2(u64 a, u64 b, u64 c) {
    u64 d; asm("fma.rn.f32x2 %0,%1,%2,%3;" : "=l"(d) : "l"(a), "l"(b), "l"(c)); return d;
}
__device__ __forceinline__ float hsum2(u64 v) {
    float lo, hi; asm("mov.b64 {%0,%1},%2;" : "=f"(lo), "=f"(hi) : "l"(v)); return lo + hi;
}
__device__ __forceinline__ void cp16(uint32_t d, const void* s) {
    asm volatile("cp.async.cg.shared.global [%0],[%1],16;" :: "r"(d), "l"(s));
}
__device__ __forceinline__ void cpcommit() { asm volatile("cp.async.commit_group;"); }
__device__ __forceinline__ void cpwait1()  { asm volatile("cp.async.wait_group 1;"); }
__device__ __forceinline__ uint32_t tf32h(float v) {
    uint32_t r; asm("cvt.rna.tf32.f32 %0, %1;" : "=r"(r) : "f"(v)); return r;
}
// m16n8k8 TF32 mma, fp32 accumulate (standard sm_80+ PTX, no arch suffix)
__device__ __forceinline__ void mma_tf32(float* c, uint32_t a0, uint32_t a1,
                                         uint32_t a2, uint32_t a3,
                                         uint32_t b0, uint32_t b1) {
    asm volatile(
        "mma.sync.aligned.m16n8k8.row.col.f32.tf32.tf32.f32 "
        "{%0,%1,%2,%3},{%4,%5,%6,%7},{%8,%9},{%0,%1,%2,%3};"
        : "+f"(c[0]), "+f"(c[1]), "+f"(c[2]), "+f"(c[3])
        : "r"(a0), "r"(a1), "r"(a2), "r"(a3), "r"(b0), "r"(b1));
}

// ---------------- Stage 1: t = x @ A^T via 3xTF32 mma.sync ----------------
// Block 128 thr / 4 warps, 64 rows, grid 256, 3 CTAs/SM.
// Warp owns rows w*16..w*16+15, all r=16 (two m16n8k8 N-tiles); accumulators
// live in registers across the whole K loop -> NO cross-warp reduction.
// x: 3-stage cp.async ring, rows of 64 f32, 16B-slot swizzle
//    phys = slot ^ (row & 15)  (conflict-free for cp stores AND frag loads).
// A: hi/lo tf32 split, transposed tiles ahT/alT[k][r] stride 24, 2 slots,
//    register-prefetched one chunk ahead.
// Schedule per chunk (R6-proven): wait1 -> barrier -> STS A -> cp x(c+2) -> compute.
__global__ void __launch_bounds__(128, 3)
lora_stage1_mma(const float* __restrict__ x, const float* __restrict__ A)
{
    extern __shared__ __align__(16) unsigned char sm[];
    float*    xs = (float*)sm;                      // 3 x 16 KB
    uint32_t* ah = (uint32_t*)(sm + 49152);         // 2 slots x 6 KB
    uint32_t* al = (uint32_t*)(sm + 49152 + 2 * AT_WORDS * 4);

    const int tid  = threadIdx.x;
    const int w    = tid >> 5;
    const int lane = tid & 31;
    const int g    = lane >> 2;       // 0..7
    const int t    = lane & 3;        // 0..3
    const long rowBase = (long)blockIdx.x * 64;

    // x cp.async role: row = tid>>1 (0..63), half = tid&1 (8 slots each)
    const int crow = tid >> 1, chalf = tid & 1;
    const float* xsrc = x + (rowBase + crow) * D + chalf * 32;
    const uint32_t xs_sh = (uint32_t)__cvta_generic_to_shared(sm);
    const uint32_t xrow_sh = xs_sh + (uint32_t)crow * 256u;
    const int crsw = crow & 15;

    // A role: r = tid&15, kseg = tid>>4 (0..7) -> k = kseg*8..+7
    const int ar = tid & 15, akseg = tid >> 4;
    const float* asrc = A + (long)ar * D + akseg * 8;

    // compute-side x addresses
    const int row_e = w * 16 + g;           // & 15 == g
    const float* base_e = xs + row_e * 64;
    const float* base_o = base_e + 8 * 64;
    const int rswe = g, rswo = g ^ 8;

    float acc[2][4] = {{0.f,0.f,0.f,0.f},{0.f,0.f,0.f,0.f}};

    // ---- prologue ----
    #pragma unroll
    for (int cc = 0; cc < 2; ++cc) {
        #pragma unroll
        for (int j = 0; j < 8; ++j) {
            const int slot = chalf * 8 + j;
            cp16(xrow_sh + (uint32_t)(cc * 16384) +
                 (uint32_t)((slot ^ crsw) << 4), xsrc + cc * KC + j * 4);
        }
        cpcommit();
    }
    {   // A(0) direct split+store
        float4 v0 = *(const float4*)(asrc);
        float4 v1 = *(const float4*)(asrc + 4);
        float vv[8] = {v0.x,v0.y,v0.z,v0.w,v1.x,v1.y,v1.z,v1.w};
        #pragma unroll
        for (int j = 0; j < 8; ++j) {
            const int k = akseg * 8 + j;
            uint32_t h = tf32h(vv[j]);
            ah[k * AT_STRIDE + ar] = h;
            al[k * AT_STRIDE + ar] = tf32h(vv[j] - __uint_as_float(h));
        }
    }
    float4 apf0 = *(const float4*)(asrc + KC);
    float4 apf1 = *(const float4*)(asrc + KC + 4);

    for (int c = 0; c < NCH; ++c) {
        cpwait1();           // x(c) landed (this thread's groups)
        __syncthreads();     // visible to all; compute(c-1) done everywhere

        // STS A(c+1) into slot (c+1)&1
        if (c + 1 < NCH) {
            uint32_t* ahp = ah + ((c + 1) & 1) * AT_WORDS;
            uint32_t* alp = al + ((c + 1) & 1) * AT_WORDS;
            float vv[8] = {apf0.x,apf0.y,apf0.z,apf0.w,apf1.x,apf1.y,apf1.z,apf1.w};
            #pragma unroll
            for (int j = 0; j < 8; ++j) {
                const int k = akseg * 8 + j;
                uint32_t h = tf32h(vv[j]);
                ahp[k * AT_STRIDE + ar] = h;
                alp[k * AT_STRIDE + ar] = tf32h(vv[j] - __uint_as_float(h));
            }
        }
        // cp.async x(c+2) into stage (c+2)%3 (safe: after barrier)
        if (c + 2 < NCH) {
            const uint32_t sbase = (uint32_t)(((c + 2) % 3) * 16384);
            #pragma unroll
            for (int j = 0; j < 8; ++j) {
                const int slot = chalf * 8 + j;
                cp16(xrow_sh + sbase + (uint32_t)((slot ^ crsw) << 4),
                     xsrc + (c + 2) * KC + j * 4);
            }
        }
        cpcommit();          // always: group count tracks chunks
        // prefetch A(c+2) (LDG hidden under compute below)
        if (c + 2 < NCH) {
            apf0 = *(const float4*)(asrc + (c + 2) * KC);
            apf1 = *(const float4*)(asrc + (c + 2) * KC + 4);
        }

        // ---- compute chunk c ----
        const float* xe = base_e + (c % 3) * 4096;
        const float* xo = base_o + (c % 3) * 4096;
        const uint32_t* ahp = ah + (c & 1) * AT_WORDS;
        const uint32_t* alp = al + (c & 1) * AT_WORDS;

        #pragma unroll
        for (int ks = 0; ks < 8; ++ks) {
            const int s0 = 2 * ks, s1 = 2 * ks + 1;
            float fe0 = xe[((s0 ^ rswe) << 2) + t];   // row g,   col 8ks+t
            float fo0 = xo[((s0 ^ rswo) << 2) + t];   // row g+8, col 8ks+t
            float fe1 = xe[((s1 ^ rswe) << 2) + t];   // row g,   col 8ks+t+4
            float fo1 = xo[((s1 ^ rswo) << 2) + t];   // row g+8, col 8ks+t+4
            uint32_t h0 = tf32h(fe0), h1 = tf32h(fo0);
            uint32_t h2 = tf32h(fe1), h3 = tf32h(fo1);
            uint32_t l0 = tf32h(fe0 - __uint_as_float(h0));
            uint32_t l1 = tf32h(fo0 - __uint_as_float(h1));
            uint32_t l2 = tf32h(fe1 - __uint_as_float(h2));
            uint32_t l3 = tf32h(fo1 - __uint_as_float(h3));
            const int kb0 = (ks * 8 + t) * AT_STRIDE;
            const int kb1 = (ks * 8 + t + 4) * AT_STRIDE;
            #pragma unroll
            for (int nt = 0; nt < 2; ++nt) {
                const int n = g + nt * 8;
                uint32_t b0h = ahp[kb0 + n], b1h = ahp[kb1 + n];
                uint32_t b0l = alp[kb0 + n], b1l = alp[kb1 + n];
                mma_tf32(acc[nt], h0, h1, h2, h3, b0h, b1h);   // xh*Ah
                mma_tf32(acc[nt], l0, l1, l2, l3, b0h, b1h);   // xl*Ah
                mma_tf32(acc[nt], h0, h1, h2, h3, b0l, b1l);   // xh*Al
            }
        }
    }

    // ---- epilogue: C frags -> g_t (no reduction needed) ----
    {
        float* ge = g_t + (rowBase + row_e) * R;
        float* go = g_t + (rowBase + row_e + 8) * R;
        #pragma unroll
        for (int nt = 0; nt < 2; ++nt) {
            *(float2*)(ge + nt * 8 + 2 * t) = make_float2(acc[nt][0], acc[nt][1]);
            *(float2*)(go + nt * 8 + 2 * t) = make_float2(acc[nt][2], acc[nt][3]);
        }
    }
}

// ---------------- Stage 2: out = t @ B^T ---------------- (R6 known-good, ~56us)
__global__ void __launch_bounds__(256, 2)
lora_stage2(const float* __restrict__ B, float* __restrict__ out)
{
    __shared__ float ts[128 * R];   // 8 KB

    const int tid = threadIdx.x;
    const long rowBase = (long)blockIdx.y * 128;
    const int ob = blockIdx.x * 1024 + tid * 4;

    *(float4*)(ts + tid * 8)     = *(const float4*)(g_t + rowBase * R + tid * 8);
    *(float4*)(ts + tid * 8 + 4) = *(const float4*)(g_t + rowBase * R + tid * 8 + 4);

    u64 bb[4][8];
    #pragma unroll
    for (int j = 0; j < 4; ++j) {
        const float* bp = B + (long)(ob + j) * R;
        ulonglong2 v0 = *(const ulonglong2*)(bp);
        ulonglong2 v1 = *(const ulonglong2*)(bp + 4);
        ulonglong2 v2 = *(const ulonglong2*)(bp + 8);
        ulonglong2 v3 = *(const ulonglong2*)(bp + 12);
        bb[j][0] = v0.x; bb[j][1] = v0.y;
        bb[j][2] = v1.x; bb[j][3] = v1.y;
        bb[j][4] = v2.x; bb[j][5] = v2.y;
        bb[j][6] = v3.x; bb[j][7] = v3.y;
    }
    __syncthreads();

    for (int row = 0; row < 128; ++row) {
        u64 tt[8];
        #pragma unroll
        for (int q = 0; q < 4; ++q) {
            ulonglong2 v = *(const ulonglong2*)(ts + row * R + q * 4);
            tt[2 * q]     = v.x;
            tt[2 * q + 1] = v.y;
        }
        float res[4];
        #pragma unroll
        for (int j = 0; j < 4; ++j) {
            u64 a = 0ULL;
            #pragma unroll
            for (int p = 0; p < 8; ++p)
                a = fma2(bb[j][p], tt[p], a);
            res[j] = hsum2(a);
        }
        *(float4*)(out + (rowBase + row) * (long)D + ob) =
            make_float4(res[0], res[1], res[2], res[3]);
    }
}

extern "C" void kernel_launch(void* const* d_in, const int* in_sizes, int n_in,
                              void* d_out, int out_size) {
    const float* x = (const float*)d_in[0];   // [16384, 4096]
    const float* A = (const float*)d_in[1];   // [16, 4096]
    const float* B = (const float*)d_in[2];   // [4096, 16]
    float* out = (float*)d_out;               // [16384, 4096]

    cudaFuncSetAttribute(lora_stage1_mma,
                         cudaFuncAttributeMaxDynamicSharedMemorySize, S1_SMEM);
    lora_stage1_mma<<<ROWS_TOTAL / 64, 128, S1_SMEM>>>(x, A);
    dim3 g2(D / 1024, ROWS_TOTAL / 128);
    lora_stage2<<<g2, 256>>>(B, out);
}